// round 16
// baseline (speedup 1.0000x reference)
#include <cuda_runtime.h>
#include <cuda_bf16.h>
#include <cstdint>

// Problem constants
#define BB   128
#define TT   1024
#define II   256
#define HH   512
#define CC   32

#define GR   8          // CTAs per group == cluster size
#define NG   16         // 16 groups (8 batches each)
#define BG   8          // batches per group
#define JS   64         // j rows per CTA

typedef unsigned long long ull;

// ---------------- generic asm helpers ----------------

__device__ __forceinline__ unsigned smem_u32(const void* p) {
    return (unsigned)__cvta_generic_to_shared(p);
}

__device__ __forceinline__ float lds32v(unsigned a) {
    float v;
    asm volatile("ld.shared.f32 %0, [%1];" : "=f"(v) : "r"(a));
    return v;
}

__device__ __forceinline__ void sts128v(unsigned a, uint4 v) {
    asm volatile("st.shared.v4.b32 [%0], {%1,%2,%3,%4};"
                 :: "r"(a), "r"(v.x), "r"(v.y), "r"(v.z), "r"(v.w) : "memory");
}

__device__ __forceinline__ void sts64u(unsigned a, uint32_t x, uint32_t y) {
    asm volatile("st.shared.v2.b32 [%0], {%1,%2};"
                 :: "r"(a), "r"(x), "r"(y) : "memory");
}

__device__ __forceinline__ void sts64f(unsigned a, float x, float y) {
    asm volatile("st.shared.v2.f32 [%0], {%1,%2};"
                 :: "r"(a), "f"(x), "f"(y) : "memory");
}

__device__ __forceinline__ void sts16(unsigned a, unsigned short v) {
    asm volatile("st.shared.u16 [%0], %1;" :: "r"(a), "h"(v) : "memory");
}

__device__ __forceinline__ void ldsm_x4(unsigned addr, uint32_t& r0, uint32_t& r1,
                                        uint32_t& r2, uint32_t& r3) {
    asm volatile("ldmatrix.sync.aligned.m8n8.x4.shared.b16 {%0,%1,%2,%3}, [%4];"
                 : "=r"(r0), "=r"(r1), "=r"(r2), "=r"(r3) : "r"(addr));
}

__device__ __forceinline__ void ldsm_x2(unsigned addr, uint32_t& r0, uint32_t& r1) {
    asm volatile("ldmatrix.sync.aligned.m8n8.x2.shared.b16 {%0,%1}, [%2];"
                 : "=r"(r0), "=r"(r1) : "r"(addr));
}

__device__ __forceinline__ void mma16816(float* c, const uint32_t* a,
                                         uint32_t b0, uint32_t b1) {
    asm volatile(
        "mma.sync.aligned.m16n8k16.row.col.f32.bf16.bf16.f32 "
        "{%0,%1,%2,%3}, {%4,%5,%6,%7}, {%8,%9}, {%0,%1,%2,%3};"
        : "+f"(c[0]), "+f"(c[1]), "+f"(c[2]), "+f"(c[3])
        : "r"(a[0]), "r"(a[1]), "r"(a[2]), "r"(a[3]), "r"(b0), "r"(b1));
}

__device__ __forceinline__ unsigned mapa_cluster(unsigned addr, unsigned rank) {
    unsigned r;
    asm("mapa.shared::cluster.u32 %0, %1, %2;" : "=r"(r) : "r"(addr), "r"(rank));
    return r;
}

__device__ __forceinline__ void cluster_sync_() {
    asm volatile("barrier.cluster.arrive.aligned;" ::: "memory");
    asm volatile("barrier.cluster.wait.aligned;" ::: "memory");
}

__device__ __forceinline__ void mbar_init(unsigned a, unsigned cnt) {
    asm volatile("mbarrier.init.shared.b64 [%0], %1;" :: "r"(a), "r"(cnt) : "memory");
}

__device__ __forceinline__ void mbar_expect(unsigned a, unsigned tx) {
    asm volatile("mbarrier.arrive.expect_tx.shared.b64 _, [%0], %1;"
                 :: "r"(a), "r"(tx) : "memory");
}

__device__ __forceinline__ void mbar_wait(unsigned a, unsigned parity) {
    unsigned done;
    asm volatile(
        "{\n\t.reg .pred p;\n\t"
        "mbarrier.try_wait.parity.acquire.cta.shared::cta.b64 p, [%1], %2;\n\t"
        "selp.b32 %0, 1, 0, p;\n\t}"
        : "=r"(done) : "r"(a), "r"(parity) : "memory");
    if (!done) {
        asm volatile(
            "{\n\t.reg .pred P1;\n\t"
            "WAIT_LOOP_%=:\n\t"
            "mbarrier.try_wait.parity.acquire.cta.shared::cta.b64 P1, [%0], %1, 0x989680;\n\t"
            "@P1 bra.uni WAIT_DONE_%=;\n\t"
            "bra.uni WAIT_LOOP_%=;\n\t"
            "WAIT_DONE_%=:\n\t}"
            :: "r"(a), "r"(parity) : "memory");
    }
}

__device__ __forceinline__ void bulk_copy_dsmem(unsigned dst, unsigned src,
                                                unsigned bytes, unsigned mbar) {
    asm volatile(
        "cp.async.bulk.shared::cluster.shared::cta.mbarrier::complete_tx::bytes "
        "[%0], [%1], %2, [%3];"
        :: "r"(dst), "r"(src), "r"(bytes), "r"(mbar) : "memory");
}

// split a float4 into bf16x2 hi/lo register pairs
__device__ __forceinline__ void split4(float4 v, uint2& hv, uint2& lv) {
    __nv_bfloat162 h01 = __floats2bfloat162_rn(v.x, v.y);
    __nv_bfloat162 h23 = __floats2bfloat162_rn(v.z, v.w);
    float l0 = v.x - __bfloat162float(h01.x);
    float l1 = v.y - __bfloat162float(h01.y);
    float l2 = v.z - __bfloat162float(h23.x);
    float l3 = v.w - __bfloat162float(h23.y);
    __nv_bfloat162 q01 = __floats2bfloat162_rn(l0, l1);
    __nv_bfloat162 q23 = __floats2bfloat162_rn(l2, l3);
    hv = make_uint2(*(uint32_t*)&h01, *(uint32_t*)&h23);
    lv = make_uint2(*(uint32_t*)&q01, *(uint32_t*)&q23);
}

// ---------------- Pre-pass: split x and W_ih into bf16 hi/lo ----------------

#define NX4 ((BB * TT * II) / 4)
#define NW4 ((HH * II) / 4)

__device__ __nv_bfloat16 g_xhi[BB * TT * II];
__device__ __nv_bfloat16 g_xlo[BB * TT * II];
__device__ __nv_bfloat16 g_whi[HH * II];
__device__ __nv_bfloat16 g_wlo[HH * II];

__global__ void __launch_bounds__(256)
cvt_kernel(const float* __restrict__ x, const float* __restrict__ w)
{
    const int stride = gridDim.x * blockDim.x;
    for (int i = blockIdx.x * blockDim.x + threadIdx.x; i < NX4 + NW4; i += stride) {
        float4 v = (i < NX4) ? ((const float4*)x)[i]
                             : ((const float4*)w)[i - NX4];
        uint2 hv, lv;
        split4(v, hv, lv);
        if (i < NX4) {
            ((uint2*)g_xhi)[i] = hv;
            ((uint2*)g_xlo)[i] = lv;
        } else {
            ((uint2*)g_whi)[i - NX4] = hv;
            ((uint2*)g_wlo)[i - NX4] = lv;
        }
    }
}

// ---------------- Kernel A: xp via mma.sync bf16 split-precision (R10) ---------

#define KC     64
#define ASTR   72
#define XA_HI  0
#define XA_LO  (128 * ASTR * 2)
#define XB_HI  (2 * 128 * ASTR * 2)
#define XB_LO  (XB_HI + 64 * ASTR * 2)
#define SMEM_X (XB_LO + 64 * ASTR * 2)

__global__ void __launch_bounds__(256)
xp_mma_kernel(const float* __restrict__ bias, float* __restrict__ out)
{
    extern __shared__ char smx[];
    const unsigned sb = smem_u32(smx);
    const int tid = threadIdx.x;
    const int wid = tid >> 5;
    const int lane = tid & 31;
    const int h0 = blockIdx.x * 64;
    const int m0 = blockIdx.y * 128;

    const int wr = wid >> 1;
    const int wc = wid & 1;

    float acc[2][4][4];
#pragma unroll
    for (int mt = 0; mt < 2; mt++)
#pragma unroll
        for (int nt = 0; nt < 4; nt++)
#pragma unroll
            for (int i = 0; i < 4; i++) acc[mt][nt][i] = 0.0f;

    const int a_row = wr * 32 + (lane & 15);
    const int a_col = (lane >> 4) * 8;
    const unsigned a_addr0 = sb + XA_HI + (unsigned)((a_row * ASTR + a_col) * 2);
    const int b_n = wc * 32 + (lane & 7) + (lane >> 4) * 8;
    const int b_k = ((lane >> 3) & 1) * 8;
    const unsigned b_addr0 = sb + XB_HI + (unsigned)((b_n * ASTR + b_k) * 2);

    for (int ch = 0; ch < 4; ch++) {
        __syncthreads();
        {
#pragma unroll
            for (int i = 0; i < 4; i++) {
                int idx = tid + i * 256;
                int row = idx >> 3;
                int c8 = idx & 7;
                size_t src = (size_t)(m0 + row) * II + ch * KC + c8 * 8;
                unsigned dst = (unsigned)((row * ASTR + c8 * 8) * 2);
                sts128v(sb + XA_HI + dst, *(const uint4*)(g_xhi + src));
                sts128v(sb + XA_LO + dst, *(const uint4*)(g_xlo + src));
            }
        }
        {
#pragma unroll
            for (int i = 0; i < 2; i++) {
                int idx = tid + i * 256;
                int row = idx >> 3;
                int c8 = idx & 7;
                size_t src = (size_t)(h0 + row) * II + ch * KC + c8 * 8;
                unsigned dst = (unsigned)((row * ASTR + c8 * 8) * 2);
                sts128v(sb + XB_HI + dst, *(const uint4*)(g_whi + src));
                sts128v(sb + XB_LO + dst, *(const uint4*)(g_wlo + src));
            }
        }
        __syncthreads();

#pragma unroll
        for (int kk = 0; kk < 4; kk++) {
            const unsigned akk = (unsigned)(kk * 16 * 2);
            uint32_t ah[2][4], al[2][4];
#pragma unroll
            for (int mt = 0; mt < 2; mt++) {
                unsigned ao = a_addr0 + akk + (unsigned)(mt * 16 * ASTR * 2);
                ldsm_x4(ao, ah[mt][0], ah[mt][1], ah[mt][2], ah[mt][3]);
                ldsm_x4(ao + (XA_LO - XA_HI),
                        al[mt][0], al[mt][1], al[mt][2], al[mt][3]);
            }
            uint32_t bh[2][4], bl[2][4];
#pragma unroll
            for (int np = 0; np < 2; np++) {
                unsigned bo = b_addr0 + akk + (unsigned)(np * 16 * ASTR * 2);
                ldsm_x4(bo, bh[np][0], bh[np][1], bh[np][2], bh[np][3]);
                ldsm_x4(bo + (XB_LO - XB_HI),
                        bl[np][0], bl[np][1], bl[np][2], bl[np][3]);
            }
#pragma unroll
            for (int mt = 0; mt < 2; mt++)
#pragma unroll
                for (int np = 0; np < 2; np++)
#pragma unroll
                    for (int sub = 0; sub < 2; sub++) {
                        float* c = acc[mt][np * 2 + sub];
                        mma16816(c, ah[mt], bh[np][sub * 2], bh[np][sub * 2 + 1]);
                        mma16816(c, ah[mt], bl[np][sub * 2], bl[np][sub * 2 + 1]);
                        mma16816(c, al[mt], bh[np][sub * 2], bh[np][sub * 2 + 1]);
                    }
        }
    }

    const int g = lane >> 2;
    const int tig = lane & 3;
#pragma unroll
    for (int mt = 0; mt < 2; mt++) {
        const int row0 = m0 + wr * 32 + mt * 16 + g;
#pragma unroll
        for (int nt = 0; nt < 4; nt++) {
            const int col = h0 + wc * 32 + nt * 8 + tig * 2;
            float2 bv = *(const float2*)&bias[col];
            float* c = acc[mt][nt];
            float2 o0 = make_float2(c[0] + bv.x, c[1] + bv.y);
            float2 o1 = make_float2(c[2] + bv.x, c[3] + bv.y);
            *(float2*)&out[(size_t)row0 * HH + col] = o0;
            *(float2*)&out[(size_t)(row0 + 8) * HH + col] = o1;
        }
    }
}

// ---------------- Kernel B ------------------------------------------------------

__device__ float g_cp[BB * HH];

__global__ void __launch_bounds__(512)
cp_kernel(const float* __restrict__ cons, const float* __restrict__ W_ch,
          const float* __restrict__ b_ch, const float* __restrict__ b_hh)
{
    __shared__ float cs[CC];
    const int b = blockIdx.x;
    const int h = threadIdx.x;
    if (h < CC) cs[h] = cons[b * CC + h];
    __syncthreads();
    float s = b_ch[h] + b_hh[h];
#pragma unroll
    for (int c = 0; c < CC; c++) s += cs[c] * W_ch[h * CC + c];
    g_cp[b * HH + h] = s;
}

// ---------------- Kernel C: recurrence, cluster DSMEM-push exchange -------------
// Cluster of 8 CTAs = one group. W fragments register-resident (R14). Per step:
// owners write their bf16 hi/lo values into the local double-buffered staged
// SMEM, then 112 threads each push one 128B row slice to a peer via
// cp.async.bulk (shared::cta -> shared::cluster) completing on the peer's
// mbarrier (expect_tx = 7 peers * 16 * 128B).
// FIXED vs R15: LOOFF = BG*WSTR*2 = 8320 bytes (hi-plane size); the previous
// /2 overlapped lo onto hi and buffer 1 onto buffer 0 -> NaN.

#define WSTR    520                   // bf16 row stride (elements)
#define WHI_OFF 0
#define WLO_OFF (JS * WSTR * 2)                 // 66560
#define HBASE   (2 * JS * WSTR * 2)             // 133120
#define LOOFF   (BG * WSTR * 2)                 // 8320 (hi->lo offset in buffer)
#define HBUFSZ  (2 * LOOFF)                     // 16640 per buffer
#define FRAG_OFF (HBASE + 2 * HBUFSZ)           // 166400
#define FRW     10
#define MBAR_OFF (FRAG_OFF + 2 * JS * FRW * 4)  // 171520
#define SMEM_C  (MBAR_OFF + 32)                 // 171552
#define TXBYTES (7u * 16u * 128u)               // 14336

__global__ void __launch_bounds__(256, 1) __cluster_dims__(GR, 1, 1)
rnn_scan_kernel(float* __restrict__ out, const float* __restrict__ W_hh,
                const int* __restrict__ lengths)
{
    extern __shared__ char smc[];
    const unsigned sb = smem_u32(smc);
    const int tid = threadIdx.x;
    const int r = blockIdx.x & 7;               // == cluster rank
    const int g = blockIdx.x >> 3;

    // one-time: convert W slice to bf16 hi/lo in SMEM
    for (int idx = tid; idx < (JS * HH) / 4; idx += 256) {
        int j = idx >> 7;
        int k4 = (idx & 127) * 4;
        float4 v = *(const float4*)&W_hh[(size_t)(r * JS + j) * HH + k4];
        uint2 hv, lv;
        split4(v, hv, lv);
        unsigned dst = sb + WHI_OFF + (unsigned)((j * WSTR + k4) * 2);
        sts64u(dst, hv.x, hv.y);
        sts64u(dst + (WLO_OFF - WHI_OFF), lv.x, lv.y);
    }
    // zero staged buffer 0 (h at t=0 is 0)
    for (int idx = tid; idx < HBUFSZ / 4; idx += 256) {
        asm volatile("st.shared.b32 [%0], %1;"
                     :: "r"(sb + HBASE + (unsigned)(idx * 4)), "r"(0u) : "memory");
    }
    if (tid == 0) {
        mbar_init(sb + MBAR_OFF, 1);
        mbar_init(sb + MBAR_OFF + 8, 1);
        mbar_expect(sb + MBAR_OFF, TXBYTES);        // buffer 0, first use (t=1)
        mbar_expect(sb + MBAR_OFF + 8, TXBYTES);    // buffer 1, first use (t=0)
    }
    __syncthreads();
    cluster_sync_();   // all mbarriers + zeroed buffers visible cluster-wide

    const int wid = tid >> 5;
    const int lane = tid & 31;
    const int mt = wid >> 1;
    const int kh = wid & 1;

    const unsigned aHi = sb + WHI_OFF +
        (unsigned)(((mt * 16 + (lane & 15)) * WSTR + kh * 256 + (lane >> 4) * 8) * 2);
    const unsigned aLo = aHi + (WLO_OFF - WHI_OFF);
    const int l4 = lane & 15;
    const unsigned bHi0 = sb + HBASE +
        (unsigned)(((l4 & 7) * WSTR + kh * 256 + ((l4 >> 3) & 1) * 8) * 2);

    const unsigned fr0 = sb + FRAG_OFF +
        (unsigned)(((kh * JS + mt * 16 + (lane >> 2)) * FRW + (lane & 3) * 2) * 4);
    const unsigned fr1 = fr0 + (unsigned)(8 * FRW * 4);

    // owner identity
    const int j0 = tid >> 3;
    const int j1 = j0 + 32;
    const int b = tid & 7;
    const int bg = g * BG + b;
    const int jg0 = r * JS + j0;
    const int jg1 = r * JS + j1;
    const int len = lengths[bg];
    const float cp0 = g_cp[bg * HH + jg0];
    const float cp1 = g_cp[bg * HH + jg1];

    float* out0 = out + (size_t)bg * TT * HH + jg0;
    float* out1 = out + (size_t)bg * TT * HH + jg1;
    float* last0 = out + (size_t)BB * TT * HH + (size_t)bg * HH + jg0;
    float* last1 = out + (size_t)BB * TT * HH + (size_t)bg * HH + jg1;

    const unsigned fo0 = sb + FRAG_OFF + (unsigned)((j0 * FRW + b) * 4);
    const unsigned fo1 = sb + FRAG_OFF + (unsigned)((j1 * FRW + b) * 4);
    const unsigned fkh = (unsigned)(JS * FRW * 4);

    // owner self-store offsets (within a staged buffer)
    const unsigned own0 = (unsigned)((b * WSTR + jg0) * 2);
    const unsigned own1 = (unsigned)((b * WSTR + jg1) * 2);

    // sender identity: threads 0..111 each push one 128B region per step
    const bool sender = tid < 112;
    unsigned snd_src = 0, snd_dst = 0, snd_mb = 0;
    if (sender) {
        const int pr = tid >> 4;            // 0..6 peer index
        const unsigned dr = (unsigned)((r + 1 + pr) & 7);
        const int q = tid & 15;
        const int bq = q >> 1;
        const int regq = q & 1;
        const unsigned off = (unsigned)(HBASE + regq * LOOFF + bq * (WSTR * 2) + r * 128);
        snd_src = sb + off;
        snd_dst = mapa_cluster(sb + off, dr);
        snd_mb = mapa_cluster(sb + MBAR_OFF, dr);
    }

    float xp0 = *out0;
    float xp1 = *out1;

    // preload W fragments into registers (invariant over t)
    uint32_t wah[16][4], wal[16][4];
#pragma unroll
    for (int ks = 0; ks < 16; ks++) {
        const unsigned ko = (unsigned)(ks * 32);
        ldsm_x4(aHi + ko, wah[ks][0], wah[ks][1], wah[ks][2], wah[ks][3]);
        ldsm_x4(aLo + ko, wal[ks][0], wal[ks][1], wal[ks][2], wal[ks][3]);
    }

    for (int t = 0; t < TT; t++) {
        const int p = t & 1;
        const int w = p ^ 1;
        const unsigned bHi = bHi0 + (unsigned)(p * HBUFSZ);
        const unsigned bLo = bHi + (unsigned)LOOFF;

        // ---- dot via tensor cores (W resident; only h loaded per step) ----
        float ca[4] = {0, 0, 0, 0}, cb[4] = {0, 0, 0, 0}, cc[4] = {0, 0, 0, 0};
#pragma unroll
        for (int ks = 0; ks < 16; ks++) {
            const unsigned ko = (unsigned)(ks * 32);
            uint32_t bh0, bh1, bl0, bl1;
            ldsm_x2(bHi + ko, bh0, bh1);
            ldsm_x2(bLo + ko, bl0, bl1);
            mma16816(ca, wah[ks], bh0, bh1);
            mma16816(cb, wah[ks], bl0, bl1);
            mma16816(cc, wal[ks], bh0, bh1);
        }
        sts64f(fr0, ca[0] + cb[0] + cc[0], ca[1] + cb[1] + cc[1]);
        sts64f(fr1, ca[2] + cb[2] + cc[2], ca[3] + cb[3] + cc[3]);
        __syncthreads();

        // ---- owner: reduce, tanh, write own values into staged buffer w ----
        float d0 = lds32v(fo0) + lds32v(fo0 + fkh);
        float d1 = lds32v(fo1) + lds32v(fo1 + fkh);

        const bool act = (t < len);
        float v0 = tanhf(d0 + xp0 + cp0);
        float v1 = tanhf(d1 + xp1 + cp1);

        const unsigned wb = sb + (unsigned)(HBASE + w * HBUFSZ);
        __nv_bfloat16 vh0 = __float2bfloat16(v0);
        __nv_bfloat16 vl0 = __float2bfloat16(v0 - __bfloat162float(vh0));
        __nv_bfloat16 vh1 = __float2bfloat16(v1);
        __nv_bfloat16 vl1 = __float2bfloat16(v1 - __bfloat162float(vh1));
        sts16(wb + own0, *(unsigned short*)&vh0);
        sts16(wb + own0 + (unsigned)LOOFF, *(unsigned short*)&vl0);
        sts16(wb + own1, *(unsigned short*)&vh1);
        sts16(wb + own1 + (unsigned)LOOFF, *(unsigned short*)&vl1);

        out0[(size_t)t * HH] = act ? v0 : 0.0f;
        out1[(size_t)t * HH] = act ? v1 : 0.0f;
        if (t == len - 1) { *last0 = v0; *last1 = v1; }

        if (t == TT - 1) break;

        __syncthreads();                        // all own values staged
        asm volatile("fence.proxy.async.shared::cta;" ::: "memory");

        // ---- push own slice to all 7 peers (one 128B bulk copy per thread) ----
        if (sender) {
            const unsigned bo = (unsigned)(w * HBUFSZ);
            bulk_copy_dsmem(snd_dst + bo, snd_src + bo, 128u,
                            snd_mb + (unsigned)(w * 8));
        }

        xp0 = out0[(size_t)(t + 1) * HH];       // prefetch under transfer window
        xp1 = out1[(size_t)(t + 1) * HH];

        // ---- wait for all peers' slices; re-arm barrier for its next use ----
        const unsigned mymb = sb + MBAR_OFF + (unsigned)(w * 8);
        const unsigned parity = (unsigned)(((t + w) >> 1) & 1);
        mbar_wait(mymb, parity);
        if (tid == 0) mbar_expect(mymb, TXBYTES);
    }

    cluster_sync_();   // keep source SMEM alive until all transfers drain
}

// ---------------- launch -------------------------------------------------------

extern "C" void kernel_launch(void* const* d_in, const int* in_sizes, int n_in,
                              void* d_out, int out_size)
{
    const float* x       = (const float*)d_in[0];
    const float* cons    = (const float*)d_in[1];
    const int*   lengths = (const int*)d_in[2];
    const float* W_ih    = (const float*)d_in[3];
    const float* b_ih    = (const float*)d_in[4];
    const float* W_hh    = (const float*)d_in[5];
    const float* b_hh    = (const float*)d_in[6];
    const float* W_ch    = (const float*)d_in[7];
    const float* b_ch    = (const float*)d_in[8];
    float* out = (float*)d_out;

    // Kernel order: cvt, xp, cp, scan (scan is the ncu-captured 4th launch)
    cvt_kernel<<<4096, 256>>>(x, W_ih);

    cudaFuncSetAttribute(xp_mma_kernel,
                         cudaFuncAttributeMaxDynamicSharedMemorySize, SMEM_X);
    xp_mma_kernel<<<dim3(8, (BB * TT) / 128), 256, SMEM_X>>>(b_ih, out);

    cp_kernel<<<BB, HH>>>(cons, W_ch, b_ch, b_hh);

    cudaFuncSetAttribute(rnn_scan_kernel,
                         cudaFuncAttributeMaxDynamicSharedMemorySize, SMEM_C);
    rnn_scan_kernel<<<NG * GR, 256, SMEM_C>>>(out, W_hh, lengths);
}